// round 16
// baseline (speedup 1.0000x reference)
#include <cuda_runtime.h>
#include <cuda_bf16.h>
#include <math_constants.h>

// SupPixPool: out[b][c][k] = max over p with spx[b][p]==k of img[b][c][p]
// B=4, C=64, H=W=512 (HW=262144), K=1024. out viewed as [256 channels][1024].
//
// R15 = R14 + depth-2 software pipeline in the scatter loop.
// Model: conflict-free ATOMS (RSUB=32: slot = k*32+lane -> bank == lane)
// needs ~16 L1 slot-cyc per 128px vs 24 for RSUB=16 -> ideal ~33us, but at
// 32 warps/SM a warp's turnaround (~512cyc) is just under DRAM latency
// (~600cyc): depth-1 prefetch (R14, 55.8us) left loads exposed. Depth-2
// gives ~1024cyc of slack -> loads fully hidden. Regs ~62 <= 64 cap.
// Fused single kernel (R14 machinery): first-tile owner initializes the
// channel accumulator + flag (all 148 CTAs co-resident -> spin is safe),
// contributors merge via global atomicMax, ticket-elected last contributor
// decodes in place and resets flags for graph replay.
// Bias +128.0f: values positive -> float order == s32 bit order -> one
// atomicMax(int) combine.

#define HW    262144
#define KSEG  1024
#define BC_TOT 256               // B*C channels
#define NCTA  148                // one CTA per SM, single wave
#define TPCH  8                  // tiles per channel
#define NTILE (BC_TOT * TPCH)    // 2048 tiles
#define TILE  (HW / TPCH)        // 32768 pixels
#define NTHR  1024
#define RSUB  32
#define BIAS  128.0f
#define NEG_INF_BITS 0xFF800000u
#define SLOT_BYTES (KSEG * RSUB * 4)   // 128 KB dynamic smem

__device__ int g_flags[BC_TOT];    // channel accumulator initialized? (self-resetting)
__device__ int g_tickets[BC_TOT];  // merge completion count (self-resetting)

// CTA owning tile t: largest i with floor(i*NTILE/NCTA) <= t.
__device__ __forceinline__ int tile_owner(int t) {
    return (int)((((long)t + 1) * NCTA - 1) / NTILE);
}

__device__ __forceinline__ void scat4(int* __restrict__ laneslot,
                                      const int4 s, const float4 v) {
    atomicMax(laneslot + s.x * RSUB, __float_as_int(v.x + BIAS));
    atomicMax(laneslot + s.y * RSUB, __float_as_int(v.y + BIAS));
    atomicMax(laneslot + s.z * RSUB, __float_as_int(v.z + BIAS));
    atomicMax(laneslot + s.w * RSUB, __float_as_int(v.w + BIAS));
}

__global__ void __launch_bounds__(NTHR, 1) sp_kernel(const float* __restrict__ img,
                                                     const int*   __restrict__ spx,
                                                     int*         __restrict__ out) {
    extern __shared__ int slots[];          // [KSEG * RSUB] = 128 KB
    __shared__ int sh_flag;

    const int tid  = threadIdx.x;
    const int lane = tid & 31;
    const int wid  = tid >> 5;

    const int t0 = (int)(((long)blockIdx.x * NTILE) / NCTA);
    const int t1 = (int)(((long)(blockIdx.x + 1) * NTILE) / NCTA);

    // ---- init slots to -inf ----
    {
        const uint4 v = make_uint4(NEG_INF_BITS, NEG_INF_BITS, NEG_INF_BITS, NEG_INF_BITS);
        uint4* s4p = reinterpret_cast<uint4*>(slots);
        #pragma unroll
        for (int i = tid; i < KSEG * RSUB / 4; i += NTHR)
            s4p[i] = v;
    }

    // ---- init global accumulator for channels whose FIRST tile we own ----
    {
        const int bc0 = (t0 + TPCH - 1) >> 3;   // first channel starting in [t0, t1)
        const int bc1 = (t1 + TPCH - 1) >> 3;
        for (int bc = bc0; bc < bc1; ++bc)
            out[bc * KSEG + tid] = (int)NEG_INF_BITS;
        __threadfence();
        __syncthreads();                        // all init writes fenced
        if (tid == 0)
            for (int bc = bc0; bc < bc1; ++bc)
                atomicExch(&g_flags[bc], 1);
    }
    __syncthreads();

    int* laneslot = slots + lane;               // + k*32 -> bank == lane (conflict-free)

    int t = t0;
    while (t < t1) {
        const int bc   = t >> 3;                    // channel of this span
        const int tend = min(t1, (bc + 1) << 3);    // tiles of bc in [t, t1)
        const int*   spxb = spx + (bc >> 6) * HW;
        const float* imgb = img + (size_t)bc * HW;

        const int p0 = (t - (bc << 3)) * TILE;
        const int N  = (tend - t) * (TILE / (NTHR * 4));   // block-iters, >= 8

        // ---- scatter: depth-2 software pipeline, 4096 px per block-iter ----
        {
            int idx = p0 + (tid << 2);
            const int step = NTHR * 4;
            int4   s0 = __ldg (reinterpret_cast<const int4*>(spxb + idx));
            float4 v0 = __ldcs(reinterpret_cast<const float4*>(imgb + idx));
            int4   s1 = __ldg (reinterpret_cast<const int4*>(spxb + idx + step));
            float4 v1 = __ldcs(reinterpret_cast<const float4*>(imgb + idx + step));
            #pragma unroll 1
            for (int i = 0; i < N - 2; ++i) {
                const int pf = idx + 2 * step;
                const int4   s2 = __ldg (reinterpret_cast<const int4*>(spxb + pf));
                const float4 v2 = __ldcs(reinterpret_cast<const float4*>(imgb + pf));
                scat4(laneslot, s0, v0);
                s0 = s1; v0 = v1;
                s1 = s2; v1 = v2;
                idx += step;
            }
            scat4(laneslot, s0, v0);
            scat4(laneslot, s1, v1);
        }
        __syncthreads();                        // scatters done before merge

        // ---- wait for channel accumulator init (usually already set) ----
        if (tid == 0)
            while (atomicAdd(&g_flags[bc], 0) == 0) { }
        __syncthreads();

        // ---- merge: warp w owns segments [w*32, w*32+32); conflict-free LDS
        //      + REDUX max; lane keeps segment wbase+lane -> coalesced atomics.
        int* outg = out + bc * KSEG;
        {
            const int wbase = wid * 32;
            int keep = (int)NEG_INF_BITS;
            #pragma unroll
            for (int i = 0; i < 32; ++i) {
                const int v = slots[(wbase + i) * RSUB + lane];
                const int m = __reduce_max_sync(0xFFFFFFFFu, v);
                if (lane == i) keep = m;
            }
            atomicMax(&outg[wbase + lane], keep);
        }

        // ---- ticket: last contributor decodes channel in place ----
        __threadfence();
        if (tid == 0) {
            const int nctb = tile_owner(bc * TPCH + TPCH - 1) - tile_owner(bc * TPCH);
            sh_flag = (atomicAdd(&g_tickets[bc], 1) == nctb);
        }
        __syncthreads();
        if (sh_flag) {
            const int w = __ldcg(&outg[tid]);
            reinterpret_cast<float*>(outg)[tid] = __int_as_float(w) - BIAS;
            if (tid == 0) { g_tickets[bc] = 0; g_flags[bc] = 0; }   // reset for replay
        }

        // ---- reset slots if another span follows ----
        if (tend < t1) {
            __syncthreads();                    // merge reads done
            const uint4 v = make_uint4(NEG_INF_BITS, NEG_INF_BITS, NEG_INF_BITS, NEG_INF_BITS);
            uint4* s4p = reinterpret_cast<uint4*>(slots);
            #pragma unroll
            for (int i = tid; i < KSEG * RSUB / 4; i += NTHR)
                s4p[i] = v;
        }
        __syncthreads();

        t = tend;
    }
}

extern "C" void kernel_launch(void* const* d_in, const int* in_sizes, int n_in,
                              void* d_out, int out_size) {
    const float* img = (const float*)d_in[0];   // [4, 64, 512, 512] f32
    const int*   spx = (const int*)d_in[1];     // [4, 512, 512] i32

    static int smem_set = 0;
    if (!smem_set) {
        cudaFuncSetAttribute(sp_kernel,
                             cudaFuncAttributeMaxDynamicSharedMemorySize, SLOT_BYTES);
        smem_set = 1;
    }

    sp_kernel<<<NCTA, NTHR, SLOT_BYTES>>>(img, spx, (int*)d_out);
}

// round 17
// speedup vs baseline: 1.3926x; 1.3926x over previous
#include <cuda_runtime.h>
#include <cuda_bf16.h>
#include <math_constants.h>

// SupPixPool: out[b][c][k] = max over p with spx[b][p]==k of img[b][c][p]
// B=4, C=64, H=W=512 (HW=262144), K=1024. out viewed as [256 channels][1024].
//
// R16 = R14 body + MOV-free batch-4 load staging.
// R15's rotating depth-2 pipeline compiled to MOV chains that WAIT on the
// incoming loads (fma% doubled, prefetch window -> 0, 74us). Fix: stage 4
// (int4,float4) pairs into distinct array registers (ptxas front-batches
// the 8 LDGs), then issue the 16 conflict-free ATOMS. In-flight = 32 warps
// x 8 x 512B = 128KB > the 72KB needed to cover DRAM latency at 128B/cyc.
// RSUB=32: slot = k*32+lane -> bank == lane -> 1 wavefront per ATOMS
// (16 L1-units/128px vs 24 for RSUB=16 -> ideal ~30us).
// Fused single kernel (validated in R14): first-tile owner initializes the
// channel accumulator + flag (148 co-resident CTAs -> spin safe), merge via
// global atomicMax, ticket-elected last contributor decodes in place and
// self-resets flags for graph replay. Bias +128.0f: positive floats ->
// float order == s32 bit order -> one atomicMax(int) combine.

#define HW    262144
#define KSEG  1024
#define BC_TOT 256               // B*C channels
#define NCTA  148                // one CTA per SM, single wave
#define TPCH  8                  // tiles per channel
#define NTILE (BC_TOT * TPCH)    // 2048 tiles
#define TILE  (HW / TPCH)        // 32768 pixels
#define NTHR  1024
#define RSUB  32
#define BIAS  128.0f
#define NEG_INF_BITS 0xFF800000u
#define SLOT_BYTES (KSEG * RSUB * 4)   // 128 KB dynamic smem

__device__ int g_flags[BC_TOT];    // channel accumulator initialized? (self-resetting)
__device__ int g_tickets[BC_TOT];  // merge completion count (self-resetting)

// CTA owning tile t: largest i with floor(i*NTILE/NCTA) <= t.
__device__ __forceinline__ int tile_owner(int t) {
    return (int)((((long)t + 1) * NCTA - 1) / NTILE);
}

__device__ __forceinline__ void scat4(int* __restrict__ laneslot,
                                      const int4 s, const float4 v) {
    atomicMax(laneslot + s.x * RSUB, __float_as_int(v.x + BIAS));
    atomicMax(laneslot + s.y * RSUB, __float_as_int(v.y + BIAS));
    atomicMax(laneslot + s.z * RSUB, __float_as_int(v.z + BIAS));
    atomicMax(laneslot + s.w * RSUB, __float_as_int(v.w + BIAS));
}

__global__ void __launch_bounds__(NTHR, 1) sp_kernel(const float* __restrict__ img,
                                                     const int*   __restrict__ spx,
                                                     int*         __restrict__ out) {
    extern __shared__ int slots[];          // [KSEG * RSUB] = 128 KB
    __shared__ int sh_flag;

    const int tid  = threadIdx.x;
    const int lane = tid & 31;
    const int wid  = tid >> 5;

    const int t0 = (int)(((long)blockIdx.x * NTILE) / NCTA);
    const int t1 = (int)(((long)(blockIdx.x + 1) * NTILE) / NCTA);

    // ---- init slots to -inf ----
    {
        const uint4 v = make_uint4(NEG_INF_BITS, NEG_INF_BITS, NEG_INF_BITS, NEG_INF_BITS);
        uint4* s4p = reinterpret_cast<uint4*>(slots);
        #pragma unroll
        for (int i = tid; i < KSEG * RSUB / 4; i += NTHR)
            s4p[i] = v;
    }

    // ---- init global accumulator for channels whose FIRST tile we own ----
    {
        const int bc0 = (t0 + TPCH - 1) >> 3;   // first channel starting in [t0, t1)
        const int bc1 = (t1 + TPCH - 1) >> 3;
        for (int bc = bc0; bc < bc1; ++bc)
            out[bc * KSEG + tid] = (int)NEG_INF_BITS;
        __threadfence();
        __syncthreads();                        // all init writes fenced
        if (tid == 0)
            for (int bc = bc0; bc < bc1; ++bc)
                atomicExch(&g_flags[bc], 1);
    }
    __syncthreads();

    int* laneslot = slots + lane;               // + k*32 -> bank == lane (conflict-free)

    int t = t0;
    while (t < t1) {
        const int bc   = t >> 3;                    // channel of this span
        const int tend = min(t1, (bc + 1) << 3);    // tiles of bc in [t, t1)
        const int*   spxb = spx + (bc >> 6) * HW;
        const float* imgb = img + (size_t)bc * HW;

        const int p0     = (t - (bc << 3)) * TILE;
        const int nbatch = (tend - t) * 2;          // (8 iters/tile) / 4 per batch

        // ---- scatter: batch-4 staged loads (MOV-free), 16 ATOMS per batch ----
        {
            const int step = NTHR * 4;
            int idx = p0 + (tid << 2);
            for (int bidx = 0; bidx < nbatch; ++bidx) {
                int4   s[4];
                float4 v[4];
                #pragma unroll
                for (int u = 0; u < 4; ++u) {
                    s[u] = __ldg (reinterpret_cast<const int4*>(spxb + idx + u * step));
                    v[u] = __ldcs(reinterpret_cast<const float4*>(imgb + idx + u * step));
                }
                #pragma unroll
                for (int u = 0; u < 4; ++u)
                    scat4(laneslot, s[u], v[u]);
                idx += 4 * step;
            }
        }
        __syncthreads();                        // scatters done before merge

        // ---- wait for channel accumulator init (usually already set) ----
        if (tid == 0)
            while (atomicAdd(&g_flags[bc], 0) == 0) { }
        __syncthreads();

        // ---- merge: warp w owns segments [w*32, w*32+32); conflict-free LDS
        //      + REDUX max; lane keeps segment wbase+lane -> coalesced atomics.
        int* outg = out + bc * KSEG;
        {
            const int wbase = wid * 32;
            int keep = (int)NEG_INF_BITS;
            #pragma unroll
            for (int i = 0; i < 32; ++i) {
                const int v = slots[(wbase + i) * RSUB + lane];
                const int m = __reduce_max_sync(0xFFFFFFFFu, v);
                if (lane == i) keep = m;
            }
            atomicMax(&outg[wbase + lane], keep);
        }

        // ---- ticket: last contributor decodes channel in place ----
        __threadfence();
        if (tid == 0) {
            const int nctb = tile_owner(bc * TPCH + TPCH - 1) - tile_owner(bc * TPCH);
            sh_flag = (atomicAdd(&g_tickets[bc], 1) == nctb);
        }
        __syncthreads();
        if (sh_flag) {
            const int w = __ldcg(&outg[tid]);
            reinterpret_cast<float*>(outg)[tid] = __int_as_float(w) - BIAS;
            if (tid == 0) { g_tickets[bc] = 0; g_flags[bc] = 0; }   // reset for replay
        }

        // ---- reset slots if another span follows ----
        if (tend < t1) {
            __syncthreads();                    // merge reads done
            const uint4 v = make_uint4(NEG_INF_BITS, NEG_INF_BITS, NEG_INF_BITS, NEG_INF_BITS);
            uint4* s4p = reinterpret_cast<uint4*>(slots);
            #pragma unroll
            for (int i = tid; i < KSEG * RSUB / 4; i += NTHR)
                s4p[i] = v;
        }
        __syncthreads();

        t = tend;
    }
}

extern "C" void kernel_launch(void* const* d_in, const int* in_sizes, int n_in,
                              void* d_out, int out_size) {
    const float* img = (const float*)d_in[0];   // [4, 64, 512, 512] f32
    const int*   spx = (const int*)d_in[1];     // [4, 512, 512] i32

    static int smem_set = 0;
    if (!smem_set) {
        cudaFuncSetAttribute(sp_kernel,
                             cudaFuncAttributeMaxDynamicSharedMemorySize, SLOT_BYTES);
        smem_set = 1;
    }

    sp_kernel<<<NCTA, NTHR, SLOT_BYTES>>>(img, spx, (int*)d_out);
}